// round 6
// baseline (speedup 1.0000x reference)
#include <cuda_runtime.h>
#include <math.h>

// Problem shapes (fixed for this problem instance)
static constexpr int IN_F = 256;
static constexpr int H    = 96;
static constexpr int OUTF = 40;
static constexpr int NMAX = 50000;
static constexpr int EMAX = 800000;
static constexpr int HC4  = H / 4;   // 24 float4 chunks per row

// ---------------- scratch (device globals; no allocation allowed) ----------
__device__ float g_x0[(size_t)NMAX * H];   // fc1 output (initial residual)
__device__ float g_xc[(size_t)NMAX * H];   // current activation
__device__ float g_hb[(size_t)NMAX * H];   // h buffer (in-place)
__device__ float g_dinv[NMAX];
__device__ int   g_deg[NMAX];
__device__ int   g_off[NMAX + 1];          // CSR offsets (by dst/col)
__device__ int   g_cur[NMAX];              // fill cursors
__device__ int2  g_epack[EMAX];            // {src row, bits(weight)} CSR-ordered
__device__ float g_stats[2 * H];           // sum, sumsq per feature (zeroed by bnfin)
__device__ float g_bn[2 * H];              // scale, shift per feature

// ---------------- graph prep (edge_index is int32: JAX x64 is disabled) ----
__global__ void zero_deg_kernel(int N) {
    int i = blockIdx.x * blockDim.x + threadIdx.x;
    if (i < N) g_deg[i] = 0;
}

__global__ void deg_kernel(const int* __restrict__ ei, int E) {
    int i = blockIdx.x * blockDim.x + threadIdx.x;
    if (i < E) atomicAdd(&g_deg[ei[E + i]], 1);
}

// Single-block scan: thread t owns a contiguous chunk. Serial chunk sum,
// one shuffle block-scan over 1024 partials, serial replay writing
// off/cur, with dinv fused into the replay.
__global__ __launch_bounds__(1024) void scan_dinv_kernel(int N) {
    const int C = (N + 1023) / 1024;
    int t = threadIdx.x;
    int start = t * C;
    int end = start + C; if (end > N) end = N;
    int local = 0;
    for (int i = start; i < end; i++) local += g_deg[i];

    // block exclusive scan of `local`
    int lane = t & 31, wid = t >> 5;
    int v = local;
#pragma unroll
    for (int o = 1; o < 32; o <<= 1) {
        int u = __shfl_up_sync(0xffffffffu, v, o);
        if (lane >= o) v += u;
    }
    __shared__ int wsum[32];
    if (lane == 31) wsum[wid] = v;
    __syncthreads();
    if (wid == 0) {
        int wv = wsum[lane];
#pragma unroll
        for (int o = 1; o < 32; o <<= 1) {
            int u = __shfl_up_sync(0xffffffffu, wv, o);
            if (lane >= o) wv += u;
        }
        wsum[lane] = wv;
    }
    __syncthreads();
    int run = v - local + (wid > 0 ? wsum[wid - 1] : 0);

    if (t == 0) g_off[0] = 0;
    for (int i = start; i < end; i++) {
        int d = g_deg[i];
        g_cur[i] = run;
        run += d;
        g_off[i + 1] = run;
        g_dinv[i] = rsqrtf((float)(d + 1));   // +1 = self loop
    }
}

// Bucket edges by destination; precompute edge weight.
__global__ void fill_kernel(const int* __restrict__ ei, int E) {
    int i = blockIdx.x * blockDim.x + threadIdx.x;
    if (i < E) {
        int r = ei[i];
        int c = ei[E + i];
        int slot = atomicAdd(&g_cur[c], 1);
        g_epack[slot] = make_int2(r, __float_as_int(g_dinv[r] * g_dinv[c]));
    }
}

// ---------------- fc1: [N,256] @ [256,96] + bias, relu --------------------
__global__ __launch_bounds__(256) void fc1_kernel(
    const float* __restrict__ X, const float* __restrict__ W,
    const float* __restrict__ B, int N)
{
    __shared__ float Xs[128][33];
    __shared__ float Ws[32][97];
    const int tx = threadIdx.x, ty = threadIdx.y;
    const int tid = ty * 16 + tx;
    const int row0 = blockIdx.x * 128;

    float acc[8][6];
#pragma unroll
    for (int r = 0; r < 8; r++)
#pragma unroll
        for (int c = 0; c < 6; c++) acc[r][c] = 0.f;

    for (int kc = 0; kc < IN_F; kc += 32) {
#pragma unroll
        for (int i = tid; i < 128 * 32; i += 256) {
            int r = i >> 5, k = i & 31;
            int gr = row0 + r;
            Xs[r][k] = (gr < N) ? X[(size_t)gr * IN_F + kc + k] : 0.f;
        }
#pragma unroll
        for (int i = tid; i < 32 * 96; i += 256) {
            int k = i / 96, j = i - 96 * k;
            Ws[k][j] = W[(size_t)(kc + k) * H + j];
        }
        __syncthreads();
#pragma unroll
        for (int kk = 0; kk < 32; kk++) {
            float a[8], bv[6];
#pragma unroll
            for (int r = 0; r < 8; r++) a[r] = Xs[ty * 8 + r][kk];
#pragma unroll
            for (int c = 0; c < 6; c++) bv[c] = Ws[kk][tx * 6 + c];
#pragma unroll
            for (int r = 0; r < 8; r++)
#pragma unroll
                for (int c = 0; c < 6; c++) acc[r][c] += a[r] * bv[c];
        }
        __syncthreads();
    }
#pragma unroll
    for (int r = 0; r < 8; r++) {
        int gr = row0 + ty * 8 + r;
        if (gr < N) {
#pragma unroll
            for (int c = 0; c < 6; c++) {
                int j = tx * 6 + c;
                float v = acc[r][c] + B[j];
                v = v > 0.f ? v : 0.f;
                g_x0[(size_t)gr * H + j] = v;
                g_xc[(size_t)gr * H + j] = v;
            }
        }
    }
}

// ---------------- aggregation (CSR gather, warp per node, high MLP) --------
// Lane l owns features l, l+32, l+64. Edge records fetched 32-at-a-time with
// one coalesced LDG.64 (lane-parallel), broadcast via shfl. Inner 32-step
// loop fully unrolled with zero-padded weights (w=0, r=0 for invalid lanes)
// so all 96 gather loads per chunk are independent -> deep MLP, latency hidden.
__global__ __launch_bounds__(256) void agg_kernel(int N) {
    int lane = threadIdx.x & 31;
    int n = blockIdx.x * 8 + (threadIdx.x >> 5);
    if (n >= N) return;
    const float* __restrict__ xc = g_xc;
    const float* xn = xc + (size_t)n * H;
    float w0 = g_dinv[n];
    w0 *= w0;
    float a0 = w0 * xn[lane];
    float a1 = w0 * xn[lane + 32];
    float a2 = w0 * xn[lane + 64];
    int s = g_off[n], e = g_off[n + 1];
    for (int base = s; base < e; base += 32) {
        int2 ep = make_int2(0, 0);               // r=0, w=0.0f padding
        if (base + lane < e) ep = g_epack[base + lane];
#pragma unroll
        for (int j = 0; j < 32; j++) {
            int   r = __shfl_sync(0xffffffffu, ep.x, j);
            float w = __int_as_float(__shfl_sync(0xffffffffu, ep.y, j));
            const float* p = xc + (size_t)r * H;
            a0 = fmaf(w, p[lane],      a0);
            a1 = fmaf(w, p[lane + 32], a1);
            a2 = fmaf(w, p[lane + 64], a2);
        }
    }
    const float* x0n = g_x0 + (size_t)n * H;
    float* hn = g_hb + (size_t)n * H;
    hn[lane]      = 0.9f * a0 + 0.1f * x0n[lane];
    hn[lane + 32] = 0.9f * a1 + 0.1f * x0n[lane + 32];
    hn[lane + 64] = 0.9f * a2 + 0.1f * x0n[lane + 64];
}

// ---------------- conv layer: h2=(1-b)*h+b*(h@W), fused BN stats -----------
__global__ __launch_bounds__(256) void conv_kernel(
    const float* __restrict__ W, float beta, int N)
{
    __shared__ float Hs[64][97];
    __shared__ float Ws[32][97];
    __shared__ float sSum[96], sSq[96];
    const int tx = threadIdx.x, ty = threadIdx.y;
    const int tid = ty * 16 + tx;
    const int row0 = blockIdx.x * 64;

    if (tid < 96) { sSum[tid] = 0.f; sSq[tid] = 0.f; }
#pragma unroll
    for (int i = tid; i < 64 * 96; i += 256) {
        int r = i / 96, k = i - 96 * r;
        int gr = row0 + r;
        Hs[r][k] = (gr < N) ? g_hb[(size_t)gr * H + k] : 0.f;
    }

    float acc[4][6];
#pragma unroll
    for (int r = 0; r < 4; r++)
#pragma unroll
        for (int c = 0; c < 6; c++) acc[r][c] = 0.f;

    for (int kc = 0; kc < H; kc += 32) {
#pragma unroll
        for (int i = tid; i < 32 * 96; i += 256) {
            int k = i / 96, j = i - 96 * k;
            Ws[k][j] = W[(size_t)(kc + k) * H + j];
        }
        __syncthreads();
#pragma unroll
        for (int kk = 0; kk < 32; kk++) {
            float a[4], bv[6];
#pragma unroll
            for (int r = 0; r < 4; r++) a[r] = Hs[ty * 4 + r][kc + kk];
#pragma unroll
            for (int c = 0; c < 6; c++) bv[c] = Ws[kk][tx * 6 + c];
#pragma unroll
            for (int r = 0; r < 4; r++)
#pragma unroll
                for (int c = 0; c < 6; c++) acc[r][c] += a[r] * bv[c];
        }
        __syncthreads();
    }

    const float onemb = 1.f - beta;
    float ls[6] = {0, 0, 0, 0, 0, 0};
    float lq[6] = {0, 0, 0, 0, 0, 0};
#pragma unroll
    for (int r = 0; r < 4; r++) {
        int gr = row0 + ty * 4 + r;
#pragma unroll
        for (int c = 0; c < 6; c++) {
            int j = tx * 6 + c;
            float h2 = onemb * Hs[ty * 4 + r][j] + beta * acc[r][c];
            if (gr >= N) h2 = 0.f;               // zero contribution to stats
            ls[c] += h2;
            lq[c] += h2 * h2;
            if (gr < N) g_hb[(size_t)gr * H + j] = h2;
        }
    }
#pragma unroll
    for (int c = 0; c < 6; c++) {
        atomicAdd(&sSum[tx * 6 + c], ls[c]);
        atomicAdd(&sSq[tx * 6 + c],  lq[c]);
    }
    __syncthreads();
    if (tid < 96) {
        atomicAdd(&g_stats[tid],      sSum[tid]);
        atomicAdd(&g_stats[96 + tid], sSq[tid]);
    }
}

// ---------------- BN finalize (also re-zeroes stats for next layer) --------
__global__ void bnfin_kernel(const float* __restrict__ gamma,
                             const float* __restrict__ bb, float invN)
{
    int j = threadIdx.x;
    if (j < H) {
        float sum = g_stats[j];
        float sq  = g_stats[H + j];
        g_stats[j] = 0.f;
        g_stats[H + j] = 0.f;
        float mean = sum * invN;
        float var  = sq * invN - mean * mean;
        float sc   = gamma[j] * rsqrtf(var + 1e-5f);
        g_bn[j]     = sc;
        g_bn[H + j] = bb[j] - mean * sc;
    }
}

// ---------------- normalize + relu -> xc -----------------------------------
__global__ void norm_relu_kernel(int N) {
    int i = blockIdx.x * blockDim.x + threadIdx.x;
    int total = N * HC4;
    if (i >= total) return;
    int j4 = i % HC4;
    float4 h  = ((const float4*)g_hb)[i];
    float4 sc = ((const float4*)g_bn)[j4];
    float4 sh = ((const float4*)(g_bn + H))[j4];
    float4 o;
    o.x = fmaxf(h.x * sc.x + sh.x, 0.f);
    o.y = fmaxf(h.y * sc.y + sh.y, 0.f);
    o.z = fmaxf(h.z * sc.z + sh.z, 0.f);
    o.w = fmaxf(h.w * sc.w + sh.w, 0.f);
    ((float4*)g_xc)[i] = o;
}

// ---------------- fc2: [N,96] @ [96,40] + bias -----------------------------
__global__ __launch_bounds__(256) void fc2_kernel(
    const float* __restrict__ W2, const float* __restrict__ B2,
    float* __restrict__ out, int N)
{
    __shared__ float Ws[96 * 40];
    int tid = threadIdx.x;
    for (int i = tid; i < 96 * 40; i += 256) Ws[i] = W2[i];
    __syncthreads();
    int warp = tid >> 5, lane = tid & 31;
    int row = blockIdx.x * 8 + warp;
    if (row >= N) return;
    const float* xr = g_xc + (size_t)row * H;
    float a0 = 0.f, a1 = 0.f;
#pragma unroll
    for (int k = 0; k < 96; k++) {
        float xv = xr[k];
        a0 += xv * Ws[k * 40 + lane];
        if (lane < 8) a1 += xv * Ws[k * 40 + 32 + lane];
    }
    out[(size_t)row * OUTF + lane] = a0 + B2[lane];
    if (lane < 8) out[(size_t)row * OUTF + 32 + lane] = a1 + B2[32 + lane];
}

// ---------------- launch ----------------------------------------------------
extern "C" void kernel_launch(void* const* d_in, const int* in_sizes, int n_in,
                              void* d_out, int out_size)
{
    const float* x     = (const float*)d_in[0];
    const int*   ei    = (const int*)d_in[1];   // int32! (JAX x64 disabled)
    const float* fc1w  = (const float*)d_in[2];
    const float* fc1b  = (const float*)d_in[3];
    const float* convw = (const float*)d_in[4];
    const float* bng   = (const float*)d_in[5];
    const float* bnb   = (const float*)d_in[6];
    const float* fc2w  = (const float*)d_in[7];
    const float* fc2b  = (const float*)d_in[8];
    float*       out   = (float*)d_out;

    int N = in_sizes[0] / IN_F;
    int E = in_sizes[1] / 2;

    dim3 t2(16, 16);
    // Order: fc1 is launch #4 so the profiler (which captures launch #4)
    // shows it next round. fc1 is independent of the graph prep; fill only
    // depends on scan.
    zero_deg_kernel<<<(N + 255) / 256, 256>>>(N);
    deg_kernel<<<(E + 255) / 256, 256>>>(ei, E);
    scan_dinv_kernel<<<1, 1024>>>(N);
    fc1_kernel<<<(N + 127) / 128, t2>>>(x, fc1w, fc1b, N);
    fill_kernel<<<(E + 255) / 256, 256>>>(ei, E);

    const double THETA = 0.5;
    int totN = N * HC4;
    for (int l = 0; l < 3; l++) {
        agg_kernel<<<(N + 7) / 8, 256>>>(N);
        float beta = (float)log(THETA / (double)(l + 1) + 1.0);
        conv_kernel<<<(N + 63) / 64, t2>>>(convw + (size_t)l * H * H, beta, N);
        bnfin_kernel<<<1, 96>>>(bng + l * H, bnb + l * H, 1.f / (float)N);
        norm_relu_kernel<<<(totN + 255) / 256, 256>>>(N);
    }
    fc2_kernel<<<(N + 7) / 8, 256>>>(fc2w, fc2b, out, N);
}

// round 7
// speedup vs baseline: 1.5758x; 1.5758x over previous
#include <cuda_runtime.h>
#include <math.h>

// Problem shapes (fixed for this problem instance)
static constexpr int IN_F = 256;
static constexpr int H    = 96;
static constexpr int OUTF = 40;
static constexpr int NMAX = 50000;
static constexpr int EMAX = 800000;
static constexpr int HC4  = H / 4;   // 24 float4 chunks per row

// ---------------- scratch (device globals; no allocation allowed) ----------
__device__ float g_x0[(size_t)NMAX * H];   // fc1 output (initial residual)
__device__ float g_xc[(size_t)NMAX * H];   // current activation
__device__ float g_hb[(size_t)NMAX * H];   // h buffer (in-place)
__device__ float g_dinv[NMAX];
__device__ int   g_deg[NMAX];
__device__ int   g_off[NMAX + 1];          // CSR offsets (by dst/col)
__device__ int   g_cur[NMAX];              // fill cursors
__device__ int2  g_epack[EMAX];            // {src row, bits(weight)} CSR-ordered
__device__ float g_stats[2 * H];           // sum, sumsq per feature (zeroed by bnfin)
__device__ float g_bn[2 * H];              // scale, shift per feature

// ---------------- graph prep (edge_index is int32: JAX x64 is disabled) ----
__global__ void zero_deg_kernel(int N) {
    int i = blockIdx.x * blockDim.x + threadIdx.x;
    if (i < N) g_deg[i] = 0;
}

__global__ void deg_kernel(const int* __restrict__ ei, int E) {
    int i = blockIdx.x * blockDim.x + threadIdx.x;
    if (i < E) atomicAdd(&g_deg[ei[E + i]], 1);
}

// Single-block scan: thread t owns a contiguous chunk. Serial chunk sum,
// shuffle block-scan over 1024 partials, serial replay writing off/cur,
// dinv fused into the replay.
__global__ __launch_bounds__(1024) void scan_dinv_kernel(int N) {
    const int C = (N + 1023) / 1024;
    int t = threadIdx.x;
    int start = t * C;
    int end = start + C; if (end > N) end = N;
    int local = 0;
    for (int i = start; i < end; i++) local += g_deg[i];

    int lane = t & 31, wid = t >> 5;
    int v = local;
#pragma unroll
    for (int o = 1; o < 32; o <<= 1) {
        int u = __shfl_up_sync(0xffffffffu, v, o);
        if (lane >= o) v += u;
    }
    __shared__ int wsum[32];
    if (lane == 31) wsum[wid] = v;
    __syncthreads();
    if (wid == 0) {
        int wv = wsum[lane];
#pragma unroll
        for (int o = 1; o < 32; o <<= 1) {
            int u = __shfl_up_sync(0xffffffffu, wv, o);
            if (lane >= o) wv += u;
        }
        wsum[lane] = wv;
    }
    __syncthreads();
    int run = v - local + (wid > 0 ? wsum[wid - 1] : 0);

    if (t == 0) g_off[0] = 0;
    for (int i = start; i < end; i++) {
        int d = g_deg[i];
        g_cur[i] = run;
        run += d;
        g_off[i + 1] = run;
        g_dinv[i] = rsqrtf((float)(d + 1));   // +1 = self loop
    }
}

// Bucket edges by destination; precompute edge weight.
__global__ void fill_kernel(const int* __restrict__ ei, int E) {
    int i = blockIdx.x * blockDim.x + threadIdx.x;
    if (i < E) {
        int r = ei[i];
        int c = ei[E + i];
        int slot = atomicAdd(&g_cur[c], 1);
        g_epack[slot] = make_int2(r, __float_as_int(g_dinv[r] * g_dinv[c]));
    }
}

// ---------------- fc1: [N,256] @ [256,96] + bias, relu --------------------
// k-major shared tiles: per kk-step operands are 2xLDS.128 + 3xLDS.64.
// launch_bounds(256,2) caps regs at 128 -> 2 blocks/SM (16 warps).
__global__ __launch_bounds__(256, 2) void fc1_kernel(
    const float* __restrict__ X, const float* __restrict__ W,
    const float* __restrict__ B, int N)
{
    __shared__ float Xs[32][132];   // [k][row], 128 rows, stride 132 (16B-aligned rows)
    __shared__ float Ws[32][98];    // [k][col], stride 98 (8B-aligned, conflict-free)
    const int tx = threadIdx.x, ty = threadIdx.y;
    const int tid = ty * 16 + tx;
    const int row0 = blockIdx.x * 128;

    // load mapping: thread covers row r = tid&127, k-halves kgrp = tid>>7
    const int lr   = tid & 127;
    const int kgrp = tid >> 7;          // 0 or 1 -> k base 0/16

    float acc[8][6];
#pragma unroll
    for (int r = 0; r < 8; r++)
#pragma unroll
        for (int c = 0; c < 6; c++) acc[r][c] = 0.f;

    for (int kc = 0; kc < IN_F; kc += 32) {
        // X tile: 4x LDG.128 per thread, scatter to k-major smem
        {
            int gr = row0 + lr;
            const float* xp = X + (size_t)gr * IN_F + kc + kgrp * 16;
#pragma unroll
            for (int m = 0; m < 4; m++) {
                float4 v = (gr < N) ? *(const float4*)(xp + 4 * m)
                                    : make_float4(0.f, 0.f, 0.f, 0.f);
                int k = kgrp * 16 + 4 * m;
                Xs[k + 0][lr] = v.x;
                Xs[k + 1][lr] = v.y;
                Xs[k + 2][lr] = v.z;
                Xs[k + 3][lr] = v.w;
            }
        }
        // W tile: 3x LDG.128 per thread (flat 32x96 chunk is contiguous)
        {
            const float* wp = W + (size_t)kc * H + tid * 12;
#pragma unroll
            for (int m = 0; m < 3; m++) {
                float4 v = *(const float4*)(wp + 4 * m);
                int f = tid * 12 + 4 * m;
                int k = f / 96, j = f - 96 * k;
                Ws[k][j + 0] = v.x;
                Ws[k][j + 1] = v.y;
                Ws[k][j + 2] = v.z;
                Ws[k][j + 3] = v.w;
            }
        }
        __syncthreads();
#pragma unroll 8
        for (int kk = 0; kk < 32; kk++) {
            float4 A0 = *(const float4*)&Xs[kk][ty * 8];
            float4 A1 = *(const float4*)&Xs[kk][ty * 8 + 4];
            float2 B0 = *(const float2*)&Ws[kk][tx * 6];
            float2 B1 = *(const float2*)&Ws[kk][tx * 6 + 2];
            float2 B2 = *(const float2*)&Ws[kk][tx * 6 + 4];
            float a[8] = {A0.x, A0.y, A0.z, A0.w, A1.x, A1.y, A1.z, A1.w};
            float bv[6] = {B0.x, B0.y, B1.x, B1.y, B2.x, B2.y};
#pragma unroll
            for (int r = 0; r < 8; r++)
#pragma unroll
                for (int c = 0; c < 6; c++) acc[r][c] = fmaf(a[r], bv[c], acc[r][c]);
        }
        __syncthreads();
    }
#pragma unroll
    for (int r = 0; r < 8; r++) {
        int gr = row0 + ty * 8 + r;
        if (gr < N) {
#pragma unroll
            for (int c = 0; c < 6; c++) {
                int j = tx * 6 + c;
                float v = acc[r][c] + B[j];
                v = v > 0.f ? v : 0.f;
                g_x0[(size_t)gr * H + j] = v;
                g_xc[(size_t)gr * H + j] = v;
            }
        }
    }
}

// ---------------- aggregation (CSR gather, float4 24-lane groups) ----------
// R3 version (measured fastest): 24 threads per node, one float4 lane each,
// 16 nodes per block; one LDG.128 per edge per lane-group.
// hb[n] = 0.9 * (dinv[n]^2 * xc[n] + sum_e w_e * xc[row_e]) + 0.1 * x0[n]
__global__ __launch_bounds__(384) void agg_kernel(int N) {
    int f4 = threadIdx.x;                    // 0..23
    int n  = blockIdx.x * 16 + threadIdx.y;
    if (n >= N) return;
    const float4* xc4 = (const float4*)g_xc;
    float w0 = g_dinv[n];
    w0 *= w0;
    float4 v = xc4[n * HC4 + f4];
    float4 acc = make_float4(w0 * v.x, w0 * v.y, w0 * v.z, w0 * v.w);
    int s = g_off[n], e = g_off[n + 1];
    for (int i = s; i < e; i++) {
        int2 ep = g_epack[i];
        float w = __int_as_float(ep.y);
        float4 xv = xc4[ep.x * HC4 + f4];
        acc.x += w * xv.x; acc.y += w * xv.y;
        acc.z += w * xv.z; acc.w += w * xv.w;
    }
    float4 x0v = ((const float4*)g_x0)[n * HC4 + f4];
    float4 h;
    h.x = 0.9f * acc.x + 0.1f * x0v.x;
    h.y = 0.9f * acc.y + 0.1f * x0v.y;
    h.z = 0.9f * acc.z + 0.1f * x0v.z;
    h.w = 0.9f * acc.w + 0.1f * x0v.w;
    ((float4*)g_hb)[n * HC4 + f4] = h;
}

// ---------------- conv layer: h2=(1-b)*h+b*(h@W), fused BN stats -----------
// k-major Hs tile: per kk-step 1xLDS.128 + 3xLDS.64 + 24 FFMA.
__global__ __launch_bounds__(256, 2) void conv_kernel(
    const float* __restrict__ W, float beta, int N)
{
    __shared__ float Hsk[96][68];   // [k][row], 64 rows, stride 68
    __shared__ float Ws[32][98];
    __shared__ float sSum[96], sSq[96];
    const int tx = threadIdx.x, ty = threadIdx.y;
    const int tid = ty * 16 + tx;
    const int row0 = blockIdx.x * 64;

    if (tid < 96) { sSum[tid] = 0.f; sSq[tid] = 0.f; }
    // load h tile (64 rows x 96 feats) k-major: 6 float4 loads per thread
    {
        int lr = tid & 63;                 // row
        int kg = (tid >> 6) * 24;          // k base: 0,24,48,72
        int gr = row0 + lr;
        const float* hp = g_hb + (size_t)gr * H + kg;
#pragma unroll
        for (int m = 0; m < 6; m++) {
            float4 v = (gr < N) ? *(const float4*)(hp + 4 * m)
                                : make_float4(0.f, 0.f, 0.f, 0.f);
            int k = kg + 4 * m;
            Hsk[k + 0][lr] = v.x;
            Hsk[k + 1][lr] = v.y;
            Hsk[k + 2][lr] = v.z;
            Hsk[k + 3][lr] = v.w;
        }
    }

    float acc[4][6];
#pragma unroll
    for (int r = 0; r < 4; r++)
#pragma unroll
        for (int c = 0; c < 6; c++) acc[r][c] = 0.f;

    for (int kc = 0; kc < H; kc += 32) {
        {
            const float* wp = W + (size_t)kc * H + tid * 12;
#pragma unroll
            for (int m = 0; m < 3; m++) {
                float4 v = *(const float4*)(wp + 4 * m);
                int f = tid * 12 + 4 * m;
                int k = f / 96, j = f - 96 * k;
                Ws[k][j + 0] = v.x;
                Ws[k][j + 1] = v.y;
                Ws[k][j + 2] = v.z;
                Ws[k][j + 3] = v.w;
            }
        }
        __syncthreads();
#pragma unroll 8
        for (int kk = 0; kk < 32; kk++) {
            float4 A0 = *(const float4*)&Hsk[kc + kk][ty * 4];
            float2 B0 = *(const float2*)&Ws[kk][tx * 6];
            float2 B1 = *(const float2*)&Ws[kk][tx * 6 + 2];
            float2 B2 = *(const float2*)&Ws[kk][tx * 6 + 4];
            float a[4] = {A0.x, A0.y, A0.z, A0.w};
            float bv[6] = {B0.x, B0.y, B1.x, B1.y, B2.x, B2.y};
#pragma unroll
            for (int r = 0; r < 4; r++)
#pragma unroll
                for (int c = 0; c < 6; c++) acc[r][c] = fmaf(a[r], bv[c], acc[r][c]);
        }
        __syncthreads();
    }

    const float onemb = 1.f - beta;
    float ls[6] = {0, 0, 0, 0, 0, 0};
    float lq[6] = {0, 0, 0, 0, 0, 0};
#pragma unroll
    for (int r = 0; r < 4; r++) {
        int gr = row0 + ty * 4 + r;
#pragma unroll
        for (int c = 0; c < 6; c++) {
            int j = tx * 6 + c;
            float h2 = onemb * Hsk[j][ty * 4 + r] + beta * acc[r][c];
            if (gr >= N) h2 = 0.f;               // zero contribution to stats
            ls[c] += h2;
            lq[c] += h2 * h2;
            if (gr < N) g_hb[(size_t)gr * H + j] = h2;
        }
    }
#pragma unroll
    for (int c = 0; c < 6; c++) {
        atomicAdd(&sSum[tx * 6 + c], ls[c]);
        atomicAdd(&sSq[tx * 6 + c],  lq[c]);
    }
    __syncthreads();
    if (tid < 96) {
        atomicAdd(&g_stats[tid],      sSum[tid]);
        atomicAdd(&g_stats[96 + tid], sSq[tid]);
    }
}

// ---------------- BN finalize (also re-zeroes stats for next layer) --------
__global__ void bnfin_kernel(const float* __restrict__ gamma,
                             const float* __restrict__ bb, float invN)
{
    int j = threadIdx.x;
    if (j < H) {
        float sum = g_stats[j];
        float sq  = g_stats[H + j];
        g_stats[j] = 0.f;
        g_stats[H + j] = 0.f;
        float mean = sum * invN;
        float var  = sq * invN - mean * mean;
        float sc   = gamma[j] * rsqrtf(var + 1e-5f);
        g_bn[j]     = sc;
        g_bn[H + j] = bb[j] - mean * sc;
    }
}

// ---------------- normalize + relu -> xc -----------------------------------
__global__ void norm_relu_kernel(int N) {
    int i = blockIdx.x * blockDim.x + threadIdx.x;
    int total = N * HC4;
    if (i >= total) return;
    int j4 = i % HC4;
    float4 h  = ((const float4*)g_hb)[i];
    float4 sc = ((const float4*)g_bn)[j4];
    float4 sh = ((const float4*)(g_bn + H))[j4];
    float4 o;
    o.x = fmaxf(h.x * sc.x + sh.x, 0.f);
    o.y = fmaxf(h.y * sc.y + sh.y, 0.f);
    o.z = fmaxf(h.z * sc.z + sh.z, 0.f);
    o.w = fmaxf(h.w * sc.w + sh.w, 0.f);
    ((float4*)g_xc)[i] = o;
}

// ---------------- fc2: [N,96] @ [96,40] + bias -----------------------------
__global__ __launch_bounds__(256) void fc2_kernel(
    const float* __restrict__ W2, const float* __restrict__ B2,
    float* __restrict__ out, int N)
{
    __shared__ float Ws[96 * 40];
    int tid = threadIdx.x;
    for (int i = tid; i < 96 * 40; i += 256) Ws[i] = W2[i];
    __syncthreads();
    int warp = tid >> 5, lane = tid & 31;
    int row = blockIdx.x * 8 + warp;
    if (row >= N) return;
    const float* xr = g_xc + (size_t)row * H;
    float a0 = 0.f, a1 = 0.f;
#pragma unroll
    for (int k = 0; k < 96; k++) {
        float xv = xr[k];
        a0 += xv * Ws[k * 40 + lane];
        if (lane < 8) a1 += xv * Ws[k * 40 + 32 + lane];
    }
    out[(size_t)row * OUTF + lane] = a0 + B2[lane];
    if (lane < 8) out[(size_t)row * OUTF + 32 + lane] = a1 + B2[32 + lane];
}

// ---------------- launch ----------------------------------------------------
extern "C" void kernel_launch(void* const* d_in, const int* in_sizes, int n_in,
                              void* d_out, int out_size)
{
    const float* x     = (const float*)d_in[0];
    const int*   ei    = (const int*)d_in[1];   // int32! (JAX x64 disabled)
    const float* fc1w  = (const float*)d_in[2];
    const float* fc1b  = (const float*)d_in[3];
    const float* convw = (const float*)d_in[4];
    const float* bng   = (const float*)d_in[5];
    const float* bnb   = (const float*)d_in[6];
    const float* fc2w  = (const float*)d_in[7];
    const float* fc2b  = (const float*)d_in[8];
    float*       out   = (float*)d_out;

    int N = in_sizes[0] / IN_F;
    int E = in_sizes[1] / 2;

    dim3 t2(16, 16);
    // fc1 is launch #4 -> gets profiled; it is independent of graph prep.
    zero_deg_kernel<<<(N + 255) / 256, 256>>>(N);
    deg_kernel<<<(E + 255) / 256, 256>>>(ei, E);
    scan_dinv_kernel<<<1, 1024>>>(N);
    fc1_kernel<<<(N + 127) / 128, t2>>>(x, fc1w, fc1b, N);
    fill_kernel<<<(E + 255) / 256, 256>>>(ei, E);

    const double THETA = 0.5;
    int totN = N * HC4;
    for (int l = 0; l < 3; l++) {
        agg_kernel<<<(N + 15) / 16, dim3(24, 16)>>>(N);
        float beta = (float)log(THETA / (double)(l + 1) + 1.0);
        conv_kernel<<<(N + 63) / 64, t2>>>(convw + (size_t)l * H * H, beta, N);
        bnfin_kernel<<<1, 96>>>(bng + l * H, bnb + l * H, 1.f / (float)N);
        norm_relu_kernel<<<(totN + 255) / 256, 256>>>(N);
    }
    fc2_kernel<<<(N + 7) / 8, 256>>>(fc2w, fc2b, out, N);
}